// round 4
// baseline (speedup 1.0000x reference)
#include <cuda_runtime.h>
#include <math.h>

// Problem dims (fixed by the dataset)
#define NB 4
#define CC 256
#define TT 16
#define HH 56
#define WW 56
#define KK 16
#define TP 8
#define HP 28
#define WP 28
#define PLANE (TT*HH*WW)        // 50176, channel stride in vw
#define OPLANE (TP*HP*WP)       // 6272, channel stride in out
#define SPLANE (HH*WW)          // 3136 spatial points per (n,t)

// Scratch: exp map, [N, T, H, W]
__device__ float g_emap[NB * TT * HH * WW];

__device__ __forceinline__ unsigned long long fma2(unsigned long long a,
                                                   unsigned long long b,
                                                   unsigned long long c) {
    unsigned long long d;
    asm("fma.rn.f32x2 %0, %1, %2, %3;" : "=l"(d) : "l"(a), "l"(b), "l"(c));
    return d;
}

__device__ __forceinline__ float lo32(unsigned long long v) {
    return __uint_as_float((unsigned)v);
}
__device__ __forceinline__ float hi32(unsigned long long v) {
    return __uint_as_float((unsigned)(v >> 32));
}

// ---------------------------------------------------------------------------
// Kernel 1: emap[n,t,h,w] = exp( max_k( sum_c w[n,k,c]*vw[n,c,t,h,w] ) / 16 )
// K is split across half-warps: lane = 16*khalf + pairIdx; 8 acc pairs/lane.
// Halves merged via shfl_xor(16). c-loop unrolled x2 so two 8-load batches
// overlap (software pipeline across batches).
// grid (14, 16, 4), block (32,7).
// ---------------------------------------------------------------------------
__global__ __launch_bounds__(224) void emap_kernel(const float* __restrict__ vw,
                                                   const float* __restrict__ wmat) {
    __shared__ unsigned long long wsp[CC * KK];  // [c][k], each {s,s} packed

    const int n = blockIdx.z;
    const int t = blockIdx.y;
    const int tid = threadIdx.y * 32 + threadIdx.x;

    // Load weights for this n into smem, duplicated into both f32x2 halves.
    const float* wn = wmat + (size_t)n * KK * CC;   // layout [k][c]
    for (int j = tid; j < KK * CC; j += 224) {
        int k = j >> 8;        // j = k*256 + c
        int c = j & 255;
        unsigned int si = __float_as_uint(wn[j]);
        wsp[c * KK + k] = ((unsigned long long)si << 32) | si;
    }
    __syncthreads();

    const int lane  = threadIdx.x;
    const int khalf = lane >> 4;                       // 0 or 1
    const int pair  = blockIdx.x * 112 + threadIdx.y * 16 + (lane & 15);

    // c=0 address for this (n,t) plane at spatial pair index `pair`
    size_t base = ((size_t)n * CC * TT + t) * SPLANE + 2 * pair;
    const unsigned long long* src = (const unsigned long long*)(vw + base);

    unsigned long long acc[8];
#pragma unroll
    for (int k = 0; k < 8; k++) acc[k] = 0ull;

    const ulonglong2* wv = (const ulonglong2*)wsp;

#pragma unroll 2
    for (int c0 = 0; c0 < CC; c0 += 8) {
        unsigned long long x[8];
#pragma unroll
        for (int u = 0; u < 8; u++)
            x[u] = __ldg(src + (size_t)u * (PLANE / 2));
        src += 8 * (size_t)(PLANE / 2);
#pragma unroll
        for (int u = 0; u < 8; u++) {
#pragma unroll
            for (int j = 0; j < 4; j++) {
                ulonglong2 wp = wv[(c0 + u) * (KK / 2) + khalf * 4 + j];
                acc[2 * j]     = fma2(wp.x, x[u], acc[2 * j]);
                acc[2 * j + 1] = fma2(wp.y, x[u], acc[2 * j + 1]);
            }
        }
    }

    float m0 = -3.4e38f, m1 = -3.4e38f;
#pragma unroll
    for (int k = 0; k < 8; k++) {
        m0 = fmaxf(m0, lo32(acc[k]));
        m1 = fmaxf(m1, hi32(acc[k]));
    }
    // merge the two k-halves
    m0 = fmaxf(m0, __shfl_xor_sync(0xffffffffu, m0, 16));
    m1 = fmaxf(m1, __shfl_xor_sync(0xffffffffu, m1, 16));

    if (khalf == 0) {
        // sqrt(C) = 16 exactly
        float e0 = expf(m0 * 0.0625f);
        float e1 = expf(m1 * 0.0625f);
        size_t eidx = ((size_t)n * TT + t) * SPLANE + 2 * pair;
        *(float2*)(g_emap + eidx) = make_float2(e0, e1);
    }
}

// ---------------------------------------------------------------------------
// Kernel 2: out[n,c,t',h',w'] = sum_{window} vw*emap / sum_{window} emap
// out_i = S_i + X_{i-1}: S_i = fma2 pair accumulation, X_i = odd-element
// cross term moved one lane right via one shfl_up per channel after the
// r-loop. FOUR channels per thread-iteration -> 36 independent LDG.64 in
// flight per warp (MLP restored to R2 level with R3's op count).
// grid (HP, TP, NB), block (32,8).
// ---------------------------------------------------------------------------
__global__ __launch_bounds__(256, 4) void pool_kernel(const float* __restrict__ vw,
                                                      float* __restrict__ out) {
    const int n  = blockIdx.z;
    const int tp = blockIdx.y;
    const int hp = blockIdx.x;
    const int lane = threadIdx.x;
    const int wl = lane < 27 ? lane : 27;  // clamp for safe address math
    const bool act = (lane < 28);

    unsigned long long ewp[9];    // packed weights for w = 2w', 2w'+1
    int rowoff[9];                // (t*H + h)*W offsets (clamped)
    float dpair = 0.f, dx = 0.f;

#pragma unroll
    for (int dt = 0; dt < 3; dt++) {
#pragma unroll
        for (int dh = 0; dh < 3; dh++) {
            const int r = dt * 3 + dh;
            const int t = 2 * tp - 1 + dt;   // max 15, only -1 possible OOB
            const int h = 2 * hp - 1 + dh;   // max 55, only -1 possible OOB
            const bool rv = (t >= 0) && (h >= 0);
            const int tc = t > 0 ? t : 0;
            const int hc = h > 0 ? h : 0;
            rowoff[r] = (tc * HH + hc) * WW;

            const float* ep = g_emap + ((size_t)n * TT + tc) * SPLANE + (size_t)hc * WW;
            float e_0 = rv ? ep[2 * wl]     : 0.f;
            float e_1 = rv ? ep[2 * wl + 1] : 0.f;
            ewp[r] = ((unsigned long long)__float_as_uint(e_1) << 32) | __float_as_uint(e_0);
            dpair += e_0 + e_1;
            dx += e_1;
        }
    }
    float dxm1 = __shfl_up_sync(0xffffffffu, dx, 1);
    if (lane == 0) dxm1 = 0.f;
    const float rden = 1.0f / (dpair + dxm1);

    const float* basep = vw + (size_t)n * CC * PLANE + 2 * wl;
    float* outb = out + ((((size_t)n * CC) * TP + tp) * HP + hp) * WP + lane;

    // Four channels per iteration; threads stride by 32 channels.
    for (int c0 = threadIdx.y * 4; c0 < CC; c0 += 32) {
        const float* pa = basep + (size_t)c0 * PLANE;
        const float* pb = pa + PLANE;
        const float* pc = pb + PLANE;
        const float* pd = pc + PLANE;
        unsigned long long accA = 0ull, accB = 0ull, accC = 0ull, accD = 0ull;
        float XA = 0.f, XB = 0.f, XC = 0.f, XD = 0.f;
#pragma unroll
        for (int r = 0; r < 9; r++) {
            const int ro = rowoff[r];
            unsigned long long xa = __ldg((const unsigned long long*)(pa + ro));
            unsigned long long xb = __ldg((const unsigned long long*)(pb + ro));
            unsigned long long xc = __ldg((const unsigned long long*)(pc + ro));
            unsigned long long xd = __ldg((const unsigned long long*)(pd + ro));
            const unsigned long long ew = ewp[r];
            accA = fma2(ew, xa, accA);
            accB = fma2(ew, xb, accB);
            accC = fma2(ew, xc, accC);
            accD = fma2(ew, xd, accD);
            const float eh = hi32(ew);
            XA = fmaf(eh, hi32(xa), XA);
            XB = fmaf(eh, hi32(xb), XB);
            XC = fmaf(eh, hi32(xc), XC);
            XD = fmaf(eh, hi32(xd), XD);
        }
        float XAm1 = __shfl_up_sync(0xffffffffu, XA, 1);
        float XBm1 = __shfl_up_sync(0xffffffffu, XB, 1);
        float XCm1 = __shfl_up_sync(0xffffffffu, XC, 1);
        float XDm1 = __shfl_up_sync(0xffffffffu, XD, 1);
        if (lane == 0) { XAm1 = 0.f; XBm1 = 0.f; XCm1 = 0.f; XDm1 = 0.f; }
        if (act) {
            outb[(size_t)(c0 + 0) * OPLANE] = (lo32(accA) + hi32(accA) + XAm1) * rden;
            outb[(size_t)(c0 + 1) * OPLANE] = (lo32(accB) + hi32(accB) + XBm1) * rden;
            outb[(size_t)(c0 + 2) * OPLANE] = (lo32(accC) + hi32(accC) + XCm1) * rden;
            outb[(size_t)(c0 + 3) * OPLANE] = (lo32(accD) + hi32(accD) + XDm1) * rden;
        }
    }
}

extern "C" void kernel_launch(void* const* d_in, const int* in_sizes, int n_in,
                              void* d_out, int out_size) {
    const float* a0 = (const float*)d_in[0];
    const float* a1 = (const float*)d_in[1];
    // vw is the big tensor (51,380,224 elems); w is 16,384 elems.
    const float* vw   = (in_sizes[0] > in_sizes[1]) ? a0 : a1;
    const float* wmat = (in_sizes[0] > in_sizes[1]) ? a1 : a0;
    float* out = (float*)d_out;

    emap_kernel<<<dim3(14, TT, NB), dim3(32, 7)>>>(vw, wmat);
    pool_kernel<<<dim3(HP, TP, NB), dim3(32, 8)>>>(vw, out);
}

// round 5
// speedup vs baseline: 1.3317x; 1.3317x over previous
#include <cuda_runtime.h>
#include <math.h>

// Problem dims (fixed by the dataset)
#define NB 4
#define CC 256
#define TT 16
#define HH 56
#define WW 56
#define KK 16
#define TP 8
#define HP 28
#define WP 28
#define PLANE (TT*HH*WW)        // 50176, channel stride in vw
#define OPLANE (TP*HP*WP)       // 6272, channel stride in out
#define SPLANE (HH*WW)          // 3136 spatial points per (n,t)

// Scratch: exp map, [N, T, H, W]
__device__ float g_emap[NB * TT * HH * WW];

__device__ __forceinline__ unsigned long long fma2(unsigned long long a,
                                                   unsigned long long b,
                                                   unsigned long long c) {
    unsigned long long d;
    asm("fma.rn.f32x2 %0, %1, %2, %3;" : "=l"(d) : "l"(a), "l"(b), "l"(c));
    return d;
}

__device__ __forceinline__ float lo32(unsigned long long v) {
    return __uint_as_float((unsigned)v);
}
__device__ __forceinline__ float hi32(unsigned long long v) {
    return __uint_as_float((unsigned)(v >> 32));
}

// ---------------------------------------------------------------------------
// Kernel 1: emap[n,t,h,w] = exp( max_k( sum_c w[n,k,c]*vw[n,c,t,h,w] ) / 16 )
// K split across half-warps: lane = 16*khalf + pairIdx; 8 acc pairs/lane
// (16 regs), x[8] load batches fit without spills. Halves merged via
// shfl_xor(16). (R3 version — no extra unroll; R4 showed it regresses.)
// grid (14, 16, 4), block (32,7).
// ---------------------------------------------------------------------------
__global__ __launch_bounds__(224) void emap_kernel(const float* __restrict__ vw,
                                                   const float* __restrict__ wmat) {
    __shared__ unsigned long long wsp[CC * KK];  // [c][k], each {s,s} packed

    const int n = blockIdx.z;
    const int t = blockIdx.y;
    const int tid = threadIdx.y * 32 + threadIdx.x;

    // Load weights for this n into smem, duplicated into both f32x2 halves.
    const float* wn = wmat + (size_t)n * KK * CC;   // layout [k][c]
    for (int j = tid; j < KK * CC; j += 224) {
        int k = j >> 8;        // j = k*256 + c
        int c = j & 255;
        unsigned int si = __float_as_uint(wn[j]);
        wsp[c * KK + k] = ((unsigned long long)si << 32) | si;
    }
    __syncthreads();

    const int lane  = threadIdx.x;
    const int khalf = lane >> 4;                       // 0 or 1
    const int pair  = blockIdx.x * 112 + threadIdx.y * 16 + (lane & 15);

    // c=0 address for this (n,t) plane at spatial pair index `pair`
    size_t base = ((size_t)n * CC * TT + t) * SPLANE + 2 * pair;
    const unsigned long long* src = (const unsigned long long*)(vw + base);

    unsigned long long acc[8];
#pragma unroll
    for (int k = 0; k < 8; k++) acc[k] = 0ull;

    const ulonglong2* wv = (const ulonglong2*)wsp;

    for (int c0 = 0; c0 < CC; c0 += 8) {
        unsigned long long x[8];
#pragma unroll
        for (int u = 0; u < 8; u++)
            x[u] = __ldg(src + (size_t)u * (PLANE / 2));
        src += 8 * (size_t)(PLANE / 2);
#pragma unroll
        for (int u = 0; u < 8; u++) {
#pragma unroll
            for (int j = 0; j < 4; j++) {
                ulonglong2 wp = wv[(c0 + u) * (KK / 2) + khalf * 4 + j];
                acc[2 * j]     = fma2(wp.x, x[u], acc[2 * j]);
                acc[2 * j + 1] = fma2(wp.y, x[u], acc[2 * j + 1]);
            }
        }
    }

    float m0 = -3.4e38f, m1 = -3.4e38f;
#pragma unroll
    for (int k = 0; k < 8; k++) {
        m0 = fmaxf(m0, lo32(acc[k]));
        m1 = fmaxf(m1, hi32(acc[k]));
    }
    // merge the two k-halves
    m0 = fmaxf(m0, __shfl_xor_sync(0xffffffffu, m0, 16));
    m1 = fmaxf(m1, __shfl_xor_sync(0xffffffffu, m1, 16));

    if (khalf == 0) {
        // sqrt(C) = 16 exactly
        float e0 = expf(m0 * 0.0625f);
        float e1 = expf(m1 * 0.0625f);
        size_t eidx = ((size_t)n * TT + t) * SPLANE + 2 * pair;
        *(float2*)(g_emap + eidx) = make_float2(e0, e1);
    }
}

// ---------------------------------------------------------------------------
// Kernel 2: out[n,c,t',h',w'] = sum_{window} vw*emap / sum_{window} emap
// R2 structure (the empirical best): 2 channels per iteration, pair LDG.64
// plus scalar L1-hit LDG.32 for the w-1 element (36 LSU ops in flight per
// iter, no cross-lane dependency in the load path, no spills at 64 regs).
// New: channels split across 2 blocks (blockIdx.z = n*2 + chalf) so the
// grid is 1792 blocks -> 3.03 waves at 4 blocks/SM instead of 1.51
// (removes the half-idle second wave).
// ---------------------------------------------------------------------------
__global__ __launch_bounds__(256, 4) void pool_kernel(const float* __restrict__ vw,
                                                      float* __restrict__ out) {
    const int n      = blockIdx.z >> 1;
    const int chalf  = blockIdx.z & 1;
    const int tp = blockIdx.y;
    const int hp = blockIdx.x;
    const int lane = threadIdx.x;
    const int wl = lane < 27 ? lane : 27;  // clamp for safe address math
    const bool act = (lane < 28);

    float ewm[9];                 // weight for w = 2w'-1
    unsigned long long ewp[9];    // packed weights for w = 2w', 2w'+1
    int rowoff[9];                // (t*H + h)*W offsets (clamped)
    float dsum = 0.f;

#pragma unroll
    for (int dt = 0; dt < 3; dt++) {
#pragma unroll
        for (int dh = 0; dh < 3; dh++) {
            const int r = dt * 3 + dh;
            const int t = 2 * tp - 1 + dt;   // max 15, only -1 possible OOB
            const int h = 2 * hp - 1 + dh;   // max 55, only -1 possible OOB
            const bool rv = (t >= 0) && (h >= 0);
            const int tc = t > 0 ? t : 0;
            const int hc = h > 0 ? h : 0;
            rowoff[r] = (tc * HH + hc) * WW;

            const float* ep = g_emap + ((size_t)n * TT + tc) * SPLANE + (size_t)hc * WW;
            const int wbase = 2 * wl - 1;
            float e_m1 = (rv && wbase >= 0) ? ep[wbase] : 0.f;
            float e_0  = rv ? ep[2 * wl]     : 0.f;
            float e_1  = rv ? ep[2 * wl + 1] : 0.f;
            ewm[r] = e_m1;
            ewp[r] = ((unsigned long long)__float_as_uint(e_1) << 32) | __float_as_uint(e_0);
            dsum += e_m1 + e_0 + e_1;
        }
    }
    const float rden = 1.0f / dsum;

    // Offset of the w-1 scalar relative to the pair base (clamped to 0 for
    // lane 0 — its weight ewm is 0 there, and vw[...+0] is finite).
    const int off_m1 = (wl > 0) ? -1 : 0;

    const float* basep = vw + (size_t)n * CC * PLANE + 2 * wl;
    float* outb = out + ((((size_t)n * CC) * TP + tp) * HP + hp) * WP + lane;

    // This block covers channels [chalf*128, chalf*128+128).
    const int cbeg = chalf * (CC / 2);
    const int cend = cbeg + (CC / 2);

    // Two channels per iteration: c0 and c0+1; threads stride by 16.
    for (int c0 = cbeg + threadIdx.y * 2; c0 < cend; c0 += 16) {
        const float* pa = basep + (size_t)c0 * PLANE;
        const float* pb = pa + PLANE;
        unsigned long long accA = 0ull, accB = 0ull;
        float sA = 0.f, sB = 0.f;
#pragma unroll
        for (int r = 0; r < 9; r++) {
            const float* ra = pa + rowoff[r];
            const float* rb = pb + rowoff[r];
            unsigned long long xa = __ldg((const unsigned long long*)ra);
            unsigned long long xb = __ldg((const unsigned long long*)rb);
            float ma = __ldg(ra + off_m1);
            float mb = __ldg(rb + off_m1);
            accA = fma2(ewp[r], xa, accA);
            accB = fma2(ewp[r], xb, accB);
            sA = fmaf(ma, ewm[r], sA);
            sB = fmaf(mb, ewm[r], sB);
        }
        if (act) {
            outb[(size_t)c0 * OPLANE]       = (lo32(accA) + hi32(accA) + sA) * rden;
            outb[(size_t)(c0 + 1) * OPLANE] = (lo32(accB) + hi32(accB) + sB) * rden;
        }
    }
}

extern "C" void kernel_launch(void* const* d_in, const int* in_sizes, int n_in,
                              void* d_out, int out_size) {
    const float* a0 = (const float*)d_in[0];
    const float* a1 = (const float*)d_in[1];
    // vw is the big tensor (51,380,224 elems); w is 16,384 elems.
    const float* vw   = (in_sizes[0] > in_sizes[1]) ? a0 : a1;
    const float* wmat = (in_sizes[0] > in_sizes[1]) ? a1 : a0;
    float* out = (float*)d_out;

    emap_kernel<<<dim3(14, TT, NB), dim3(32, 7)>>>(vw, wmat);
    pool_kernel<<<dim3(HP, TP, NB * 2), dim3(32, 8)>>>(vw, out);
}

// round 6
// speedup vs baseline: 1.4971x; 1.1242x over previous
#include <cuda_runtime.h>
#include <math.h>

// Problem dims (fixed by the dataset)
#define NB 4
#define CC 256
#define TT 16
#define HH 56
#define WW 56
#define KK 16
#define TP 8
#define HP 28
#define WP 28
#define PLANE (TT*HH*WW)        // 50176, channel stride in vw
#define OPLANE (TP*HP*WP)       // 6272, channel stride in out
#define SPLANE (HH*WW)          // 3136 spatial points per (n,t)

// Scratch: exp map, [N, T, H, W]
__device__ float g_emap[NB * TT * HH * WW];

__device__ __forceinline__ unsigned long long fma2(unsigned long long a,
                                                   unsigned long long b,
                                                   unsigned long long c) {
    unsigned long long d;
    asm("fma.rn.f32x2 %0, %1, %2, %3;" : "=l"(d) : "l"(a), "l"(b), "l"(c));
    return d;
}

__device__ __forceinline__ float lo32(unsigned long long v) {
    return __uint_as_float((unsigned)v);
}
__device__ __forceinline__ float hi32(unsigned long long v) {
    return __uint_as_float((unsigned)(v >> 32));
}

// ---------------------------------------------------------------------------
// Kernel 1: emap[n,t,h,w] = exp( max_k( sum_c w[n,k,c]*vw[n,c,t,h,w] ) / 16 )
// Half-warp K-split (8 k per lane) AND two spatial pairs per lane (pairs
// i and i+16 of the warp's 32-pair strip). Per warp per c: 2 LDG.64
// (256B, no duplicated lanes), 2 LDS.128 (weights, shared across both
// pairs), 16 FMA2 -> 0.63 warp-instr per pair per channel (was 0.81) and
// half the smem traffic per pair. 49 warps exactly cover the 1568 pairs
// of one (n,t) plane: grid (7,16,4), block (32,7) -> 448 blocks = one wave.
// ---------------------------------------------------------------------------
__global__ __launch_bounds__(224, 3) void emap_kernel(const float* __restrict__ vw,
                                                      const float* __restrict__ wmat) {
    __shared__ unsigned long long wsp[CC * KK];  // [c][k], each {s,s} packed

    const int n = blockIdx.z;
    const int t = blockIdx.y;
    const int tid = threadIdx.y * 32 + threadIdx.x;

    // Load weights for this n into smem, duplicated into both f32x2 halves.
    const float* wn = wmat + (size_t)n * KK * CC;   // layout [k][c]
    for (int j = tid; j < KK * CC; j += 224) {
        int k = j >> 8;        // j = k*256 + c
        int c = j & 255;
        unsigned int si = __float_as_uint(wn[j]);
        wsp[c * KK + k] = ((unsigned long long)si << 32) | si;
    }
    __syncthreads();

    const int lane  = threadIdx.x;
    const int khalf = lane >> 4;                       // 0 or 1
    const int li    = lane & 15;
    // This warp's 32-pair strip within the (n,t) plane.
    const int wg    = blockIdx.x * 7 + threadIdx.y;    // 0..48
    const int pairA = wg * 32 + li;                    // pairs 0..15 of strip
    // pairB = pairA + 16

    // c=0 addresses (as 8-byte pair pointers)
    size_t baseA = ((size_t)n * CC * TT + t) * SPLANE + 2 * pairA;
    const unsigned long long* srcA = (const unsigned long long*)(vw + baseA);
    const unsigned long long* srcB = srcA + 16;   // +16 pairs = +32 floats

    unsigned long long accA[8], accB[8];
#pragma unroll
    for (int k = 0; k < 8; k++) { accA[k] = 0ull; accB[k] = 0ull; }

    const ulonglong2* wv = (const ulonglong2*)wsp;

    for (int c0 = 0; c0 < CC; c0 += 4) {
        unsigned long long xA[4], xB[4];
#pragma unroll
        for (int u = 0; u < 4; u++) {
            xA[u] = __ldg(srcA + (size_t)u * (PLANE / 2));
            xB[u] = __ldg(srcB + (size_t)u * (PLANE / 2));
        }
        srcA += 4 * (size_t)(PLANE / 2);
        srcB += 4 * (size_t)(PLANE / 2);
#pragma unroll
        for (int u = 0; u < 4; u++) {
            ulonglong2 wp0 = wv[(c0 + u) * (KK / 2) + khalf * 4 + 0];
            ulonglong2 wp1 = wv[(c0 + u) * (KK / 2) + khalf * 4 + 1];
            accA[0] = fma2(wp0.x, xA[u], accA[0]);
            accA[1] = fma2(wp0.y, xA[u], accA[1]);
            accB[0] = fma2(wp0.x, xB[u], accB[0]);
            accB[1] = fma2(wp0.y, xB[u], accB[1]);
            accA[2] = fma2(wp1.x, xA[u], accA[2]);
            accA[3] = fma2(wp1.y, xA[u], accA[3]);
            accB[2] = fma2(wp1.x, xB[u], accB[2]);
            accB[3] = fma2(wp1.y, xB[u], accB[3]);
            ulonglong2 wp2 = wv[(c0 + u) * (KK / 2) + khalf * 4 + 2];
            ulonglong2 wp3 = wv[(c0 + u) * (KK / 2) + khalf * 4 + 3];
            accA[4] = fma2(wp2.x, xA[u], accA[4]);
            accA[5] = fma2(wp2.y, xA[u], accA[5]);
            accB[4] = fma2(wp2.x, xB[u], accB[4]);
            accB[5] = fma2(wp2.y, xB[u], accB[5]);
            accA[6] = fma2(wp3.x, xA[u], accA[6]);
            accA[7] = fma2(wp3.y, xA[u], accA[7]);
            accB[6] = fma2(wp3.x, xB[u], accB[6]);
            accB[7] = fma2(wp3.y, xB[u], accB[7]);
        }
    }

    float mA0 = -3.4e38f, mA1 = -3.4e38f, mB0 = -3.4e38f, mB1 = -3.4e38f;
#pragma unroll
    for (int k = 0; k < 8; k++) {
        mA0 = fmaxf(mA0, lo32(accA[k]));
        mA1 = fmaxf(mA1, hi32(accA[k]));
        mB0 = fmaxf(mB0, lo32(accB[k]));
        mB1 = fmaxf(mB1, hi32(accB[k]));
    }
    // merge the two k-halves (lane i <-> lane i+16 hold the same pairs)
    mA0 = fmaxf(mA0, __shfl_xor_sync(0xffffffffu, mA0, 16));
    mA1 = fmaxf(mA1, __shfl_xor_sync(0xffffffffu, mA1, 16));
    mB0 = fmaxf(mB0, __shfl_xor_sync(0xffffffffu, mB0, 16));
    mB1 = fmaxf(mB1, __shfl_xor_sync(0xffffffffu, mB1, 16));

    if (khalf == 0) {
        // sqrt(C) = 16 exactly
        size_t eidx = ((size_t)n * TT + t) * SPLANE + 2 * pairA;
        *(float2*)(g_emap + eidx) =
            make_float2(expf(mA0 * 0.0625f), expf(mA1 * 0.0625f));
        *(float2*)(g_emap + eidx + 32) =
            make_float2(expf(mB0 * 0.0625f), expf(mB1 * 0.0625f));
    }
}

// ---------------------------------------------------------------------------
// Kernel 2 (unchanged from R5 — empirical best): 2 channels/iter, pair
// LDG.64 + scalar L1-hit LDG.32 for the w-1 element; channels split across
// 2 blocks for wave balance.
// ---------------------------------------------------------------------------
__global__ __launch_bounds__(256, 4) void pool_kernel(const float* __restrict__ vw,
                                                      float* __restrict__ out) {
    const int n      = blockIdx.z >> 1;
    const int chalf  = blockIdx.z & 1;
    const int tp = blockIdx.y;
    const int hp = blockIdx.x;
    const int lane = threadIdx.x;
    const int wl = lane < 27 ? lane : 27;  // clamp for safe address math
    const bool act = (lane < 28);

    float ewm[9];                 // weight for w = 2w'-1
    unsigned long long ewp[9];    // packed weights for w = 2w', 2w'+1
    int rowoff[9];                // (t*H + h)*W offsets (clamped)
    float dsum = 0.f;

#pragma unroll
    for (int dt = 0; dt < 3; dt++) {
#pragma unroll
        for (int dh = 0; dh < 3; dh++) {
            const int r = dt * 3 + dh;
            const int t = 2 * tp - 1 + dt;   // max 15, only -1 possible OOB
            const int h = 2 * hp - 1 + dh;   // max 55, only -1 possible OOB
            const bool rv = (t >= 0) && (h >= 0);
            const int tc = t > 0 ? t : 0;
            const int hc = h > 0 ? h : 0;
            rowoff[r] = (tc * HH + hc) * WW;

            const float* ep = g_emap + ((size_t)n * TT + tc) * SPLANE + (size_t)hc * WW;
            const int wbase = 2 * wl - 1;
            float e_m1 = (rv && wbase >= 0) ? ep[wbase] : 0.f;
            float e_0  = rv ? ep[2 * wl]     : 0.f;
            float e_1  = rv ? ep[2 * wl + 1] : 0.f;
            ewm[r] = e_m1;
            ewp[r] = ((unsigned long long)__float_as_uint(e_1) << 32) | __float_as_uint(e_0);
            dsum += e_m1 + e_0 + e_1;
        }
    }
    const float rden = 1.0f / dsum;

    // Offset of the w-1 scalar relative to the pair base (clamped to 0 for
    // lane 0 — its weight ewm is 0 there, and vw[...+0] is finite).
    const int off_m1 = (wl > 0) ? -1 : 0;

    const float* basep = vw + (size_t)n * CC * PLANE + 2 * wl;
    float* outb = out + ((((size_t)n * CC) * TP + tp) * HP + hp) * WP + lane;

    // This block covers channels [chalf*128, chalf*128+128).
    const int cbeg = chalf * (CC / 2);
    const int cend = cbeg + (CC / 2);

    // Two channels per iteration: c0 and c0+1; threads stride by 16.
    for (int c0 = cbeg + threadIdx.y * 2; c0 < cend; c0 += 16) {
        const float* pa = basep + (size_t)c0 * PLANE;
        const float* pb = pa + PLANE;
        unsigned long long accA = 0ull, accB = 0ull;
        float sA = 0.f, sB = 0.f;
#pragma unroll
        for (int r = 0; r < 9; r++) {
            const float* ra = pa + rowoff[r];
            const float* rb = pb + rowoff[r];
            unsigned long long xa = __ldg((const unsigned long long*)ra);
            unsigned long long xb = __ldg((const unsigned long long*)rb);
            float ma = __ldg(ra + off_m1);
            float mb = __ldg(rb + off_m1);
            accA = fma2(ewp[r], xa, accA);
            accB = fma2(ewp[r], xb, accB);
            sA = fmaf(ma, ewm[r], sA);
            sB = fmaf(mb, ewm[r], sB);
        }
        if (act) {
            outb[(size_t)c0 * OPLANE]       = (lo32(accA) + hi32(accA) + sA) * rden;
            outb[(size_t)(c0 + 1) * OPLANE] = (lo32(accB) + hi32(accB) + sB) * rden;
        }
    }
}

extern "C" void kernel_launch(void* const* d_in, const int* in_sizes, int n_in,
                              void* d_out, int out_size) {
    const float* a0 = (const float*)d_in[0];
    const float* a1 = (const float*)d_in[1];
    // vw is the big tensor (51,380,224 elems); w is 16,384 elems.
    const float* vw   = (in_sizes[0] > in_sizes[1]) ? a0 : a1;
    const float* wmat = (in_sizes[0] > in_sizes[1]) ? a1 : a0;
    float* out = (float*)d_out;

    emap_kernel<<<dim3(7, TT, NB), dim3(32, 7)>>>(vw, wmat);
    pool_kernel<<<dim3(HP, TP, NB * 2), dim3(32, 8)>>>(vw, out);
}

// round 7
// speedup vs baseline: 1.4988x; 1.0011x over previous
#include <cuda_runtime.h>
#include <math.h>

// Problem dims (fixed by the dataset)
#define NB 4
#define CC 256
#define TT 16
#define HH 56
#define WW 56
#define KK 16
#define TP 8
#define HP 28
#define WP 28
#define PLANE (TT*HH*WW)        // 50176, channel stride in vw
#define OPLANE (TP*HP*WP)       // 6272, channel stride in out
#define SPLANE (HH*WW)          // 3136 spatial points per (n,t)

// Scratch: exp map, [N, T, H, W]
__device__ float g_emap[NB * TT * HH * WW];

__device__ __forceinline__ unsigned long long fma2(unsigned long long a,
                                                   unsigned long long b,
                                                   unsigned long long c) {
    unsigned long long d;
    asm("fma.rn.f32x2 %0, %1, %2, %3;" : "=l"(d) : "l"(a), "l"(b), "l"(c));
    return d;
}

__device__ __forceinline__ float lo32(unsigned long long v) {
    return __uint_as_float((unsigned)v);
}
__device__ __forceinline__ float hi32(unsigned long long v) {
    return __uint_as_float((unsigned)(v >> 32));
}

// ---------------------------------------------------------------------------
// Kernel 1: emap[n,t,h,w] = exp( max_k( sum_c w[n,k,c]*vw[n,c,t,h,w] ) / 16 )
// Half-warp K-split + two spatial pairs per lane (R6 structure). Now at
// 4 blocks/SM for higher occupancy (33% -> 44%).
// grid (7,16,4), block (32,7).
// ---------------------------------------------------------------------------
__global__ __launch_bounds__(224, 4) void emap_kernel(const float* __restrict__ vw,
                                                      const float* __restrict__ wmat) {
    __shared__ unsigned long long wsp[CC * KK];  // [c][k], each {s,s} packed

    const int n = blockIdx.z;
    const int t = blockIdx.y;
    const int tid = threadIdx.y * 32 + threadIdx.x;

    // Load weights for this n into smem, duplicated into both f32x2 halves.
    const float* wn = wmat + (size_t)n * KK * CC;   // layout [k][c]
    for (int j = tid; j < KK * CC; j += 224) {
        int k = j >> 8;        // j = k*256 + c
        int c = j & 255;
        unsigned int si = __float_as_uint(wn[j]);
        wsp[c * KK + k] = ((unsigned long long)si << 32) | si;
    }
    __syncthreads();

    const int lane  = threadIdx.x;
    const int khalf = lane >> 4;                       // 0 or 1
    const int li    = lane & 15;
    const int wg    = blockIdx.x * 7 + threadIdx.y;    // 0..48
    const int pairA = wg * 32 + li;                    // pairs 0..15 of strip

    size_t baseA = ((size_t)n * CC * TT + t) * SPLANE + 2 * pairA;
    const unsigned long long* srcA = (const unsigned long long*)(vw + baseA);
    const unsigned long long* srcB = srcA + 16;   // +16 pairs = +32 floats

    unsigned long long accA[8], accB[8];
#pragma unroll
    for (int k = 0; k < 8; k++) { accA[k] = 0ull; accB[k] = 0ull; }

    const ulonglong2* wv = (const ulonglong2*)wsp;

    for (int c0 = 0; c0 < CC; c0 += 4) {
        unsigned long long xA[4], xB[4];
#pragma unroll
        for (int u = 0; u < 4; u++) {
            xA[u] = __ldg(srcA + (size_t)u * (PLANE / 2));
            xB[u] = __ldg(srcB + (size_t)u * (PLANE / 2));
        }
        srcA += 4 * (size_t)(PLANE / 2);
        srcB += 4 * (size_t)(PLANE / 2);
#pragma unroll
        for (int u = 0; u < 4; u++) {
            ulonglong2 wp0 = wv[(c0 + u) * (KK / 2) + khalf * 4 + 0];
            ulonglong2 wp1 = wv[(c0 + u) * (KK / 2) + khalf * 4 + 1];
            accA[0] = fma2(wp0.x, xA[u], accA[0]);
            accA[1] = fma2(wp0.y, xA[u], accA[1]);
            accB[0] = fma2(wp0.x, xB[u], accB[0]);
            accB[1] = fma2(wp0.y, xB[u], accB[1]);
            accA[2] = fma2(wp1.x, xA[u], accA[2]);
            accA[3] = fma2(wp1.y, xA[u], accA[3]);
            accB[2] = fma2(wp1.x, xB[u], accB[2]);
            accB[3] = fma2(wp1.y, xB[u], accB[3]);
            ulonglong2 wp2 = wv[(c0 + u) * (KK / 2) + khalf * 4 + 2];
            ulonglong2 wp3 = wv[(c0 + u) * (KK / 2) + khalf * 4 + 3];
            accA[4] = fma2(wp2.x, xA[u], accA[4]);
            accA[5] = fma2(wp2.y, xA[u], accA[5]);
            accB[4] = fma2(wp2.x, xB[u], accB[4]);
            accB[5] = fma2(wp2.y, xB[u], accB[5]);
            accA[6] = fma2(wp3.x, xA[u], accA[6]);
            accA[7] = fma2(wp3.y, xA[u], accA[7]);
            accB[6] = fma2(wp3.x, xB[u], accB[6]);
            accB[7] = fma2(wp3.y, xB[u], accB[7]);
        }
    }

    float mA0 = -3.4e38f, mA1 = -3.4e38f, mB0 = -3.4e38f, mB1 = -3.4e38f;
#pragma unroll
    for (int k = 0; k < 8; k++) {
        mA0 = fmaxf(mA0, lo32(accA[k]));
        mA1 = fmaxf(mA1, hi32(accA[k]));
        mB0 = fmaxf(mB0, lo32(accB[k]));
        mB1 = fmaxf(mB1, hi32(accB[k]));
    }
    mA0 = fmaxf(mA0, __shfl_xor_sync(0xffffffffu, mA0, 16));
    mA1 = fmaxf(mA1, __shfl_xor_sync(0xffffffffu, mA1, 16));
    mB0 = fmaxf(mB0, __shfl_xor_sync(0xffffffffu, mB0, 16));
    mB1 = fmaxf(mB1, __shfl_xor_sync(0xffffffffu, mB1, 16));

    if (khalf == 0) {
        size_t eidx = ((size_t)n * TT + t) * SPLANE + 2 * pairA;
        *(float2*)(g_emap + eidx) =
            make_float2(expf(mA0 * 0.0625f), expf(mA1 * 0.0625f));
        *(float2*)(g_emap + eidx + 32) =
            make_float2(expf(mB0 * 0.0625f), expf(mB1 * 0.0625f));
    }
}

// ---------------------------------------------------------------------------
// Kernel 2: out = box(vw*emap) / box(emap), stride 2, win 3, pad 1.
// Restructured: lane owns an OUTPUT PAIR w' = (2*w2, 2*w2+1) whose combined
// window is 5 contiguous floats -> per row: 1 LDG.128 + 1 LDG.32. Lane
// halves (lane>>4) carry different channels; each lane processes 2 channels
// per iteration (36 gmem loads in flight). Window weights (channel-invariant,
// previously replicated in regs across all 8 y-threads) live in smem.
// Stores are STG.64. grid (HP, TP, NB*2), block (32,8).
// ---------------------------------------------------------------------------
__global__ __launch_bounds__(256, 4) void pool_kernel(const float* __restrict__ vw,
                                                      float* __restrict__ out) {
    const int n     = blockIdx.z >> 1;
    const int chalf = blockIdx.z & 1;
    const int tp = blockIdx.y;
    const int hp = blockIdx.x;
    const int tid = threadIdx.y * 32 + threadIdx.x;

    __shared__ float4 wpk[9 * 14];   // {e[4w2], e[4w2+1], e[4w2+2], e[4w2+3]} per (r,w2)
    __shared__ float  wem[9 * 14];   // e[4w2-1]
    __shared__ float  wrd[14 * 2];   // 1/denominator for outputs (2w2, 2w2+1)

    // Fill window-weight tables (126 items).
    if (tid < 126) {
        const int r  = tid / 14;
        const int w2 = tid - r * 14;
        const int dt = r / 3, dh = r - dt * 3;
        const int t = 2 * tp - 1 + dt;
        const int h = 2 * hp - 1 + dh;
        const bool rv = (t >= 0) && (h >= 0);
        const int tc = t > 0 ? t : 0;
        const int hc = h > 0 ? h : 0;
        const float* ep = g_emap + ((size_t)n * TT + tc) * SPLANE + (size_t)hc * WW;
        const int wb = 4 * w2;
        float em1 = (rv && wb > 0) ? ep[wb - 1] : 0.f;
        float e0 = rv ? ep[wb + 0] : 0.f;
        float e1 = rv ? ep[wb + 1] : 0.f;
        float e2 = rv ? ep[wb + 2] : 0.f;
        float e3 = rv ? ep[wb + 3] : 0.f;
        wpk[tid] = make_float4(e0, e1, e2, e3);
        wem[tid] = em1;
    }
    __syncthreads();
    if (tid < 28) {
        const int w2 = tid & 15 < 14 ? (tid % 14) : 0;  // 0..13
        const int sel = tid / 14;
        float s = 0.f;
#pragma unroll
        for (int r = 0; r < 9; r++) {
            float4 f = wpk[r * 14 + (tid % 14)];
            s += sel ? (f.y + f.z + f.w) : (wem[r * 14 + (tid % 14)] + f.x + f.y);
        }
        wrd[(tid % 14) * 2 + sel] = 1.0f / s;
    }
    __syncthreads();

    const int lane = threadIdx.x;
    const int w2   = (lane & 15) < 14 ? (lane & 15) : 13;  // clamp
    const int csel = lane >> 4;                            // channel select 0/1
    const bool act = (lane & 15) < 14;

    const float rden0 = wrd[w2 * 2 + 0];
    const float rden1 = wrd[w2 * 2 + 1];

    int rowoff[9];
#pragma unroll
    for (int r = 0; r < 9; r++) {
        const int dt = r / 3, dh = r - dt * 3;
        const int t = 2 * tp - 1 + dt;
        const int h = 2 * hp - 1 + dh;
        const int tc = t > 0 ? t : 0;
        const int hc = h > 0 ? h : 0;
        rowoff[r] = (tc * HH + hc) * WW;
    }
    const int off_m1 = (w2 > 0) ? -1 : 0;

    const float* basep = vw + (size_t)n * CC * PLANE + 4 * w2;
    // out offset for channel c: ((n*CC + c)*TP + tp)*HP*WP + hp*WP + 2*w2
    float* outbase = out + (((size_t)n * CC * TP + tp) * HP + hp) * WP + 2 * w2;

    const int cbeg = chalf * (CC / 2);
    const ulonglong2* wpk2 = (const ulonglong2*)wpk;

    // 4 channels per warp-iteration: this lane handles cA=c0+2*csel, cB=cA+1.
    for (int c0 = cbeg + threadIdx.y * 4; c0 < cbeg + CC / 2; c0 += 32) {
        const int cA = c0 + 2 * csel;
        const float* pA = basep + (size_t)cA * PLANE;
        const float* pB = pA + PLANE;
        unsigned long long a0A = 0ull, a1A = 0ull, a0B = 0ull, a1B = 0ull;
        float smA = 0.f, sxA = 0.f, smB = 0.f, sxB = 0.f;
#pragma unroll
        for (int r = 0; r < 9; r++) {
            const float* rA = pA + rowoff[r];
            const float* rB = pB + rowoff[r];
            ulonglong2 xA = __ldg((const ulonglong2*)rA);
            ulonglong2 xB = __ldg((const ulonglong2*)rB);
            float mA = __ldg(rA + off_m1);
            float mB = __ldg(rB + off_m1);
            ulonglong2 wpr = wpk2[r * 14 + w2];   // .x = (e0,e1), .y = (e2,e3)
            float em1 = wem[r * 14 + w2];
            a0A = fma2(wpr.x, xA.x, a0A);
            a1A = fma2(wpr.y, xA.y, a1A);
            a0B = fma2(wpr.x, xB.x, a0B);
            a1B = fma2(wpr.y, xB.y, a1B);
            smA = fmaf(em1, mA, smA);
            smB = fmaf(em1, mB, smB);
            sxA = fmaf(hi32(wpr.x), hi32(xA.x), sxA);
            sxB = fmaf(hi32(wpr.x), hi32(xB.x), sxB);
        }
        if (act) {
            float2 oA = make_float2((lo32(a0A) + hi32(a0A) + smA) * rden0,
                                    (lo32(a1A) + hi32(a1A) + sxA) * rden1);
            float2 oB = make_float2((lo32(a0B) + hi32(a0B) + smB) * rden0,
                                    (lo32(a1B) + hi32(a1B) + sxB) * rden1);
            *(float2*)(outbase + (size_t)cA * OPLANE) = oA;
            *(float2*)(outbase + (size_t)(cA + 1) * OPLANE) = oB;
        }
    }
}

extern "C" void kernel_launch(void* const* d_in, const int* in_sizes, int n_in,
                              void* d_out, int out_size) {
    const float* a0 = (const float*)d_in[0];
    const float* a1 = (const float*)d_in[1];
    // vw is the big tensor (51,380,224 elems); w is 16,384 elems.
    const float* vw   = (in_sizes[0] > in_sizes[1]) ? a0 : a1;
    const float* wmat = (in_sizes[0] > in_sizes[1]) ? a1 : a0;
    float* out = (float*)d_out;

    emap_kernel<<<dim3(7, TT, NB), dim3(32, 7)>>>(vw, wmat);
    pool_kernel<<<dim3(HP, TP, NB * 2), dim3(32, 8)>>>(vw, out);
}

// round 8
// speedup vs baseline: 1.6828x; 1.1228x over previous
#include <cuda_runtime.h>
#include <math.h>

// Problem dims (fixed by the dataset)
#define NB 4
#define CC 256
#define TT 16
#define HH 56
#define WW 56
#define KK 16
#define TP 8
#define HP 28
#define WP 28
#define PLANE (TT*HH*WW)        // 50176, channel stride in vw
#define OPLANE (TP*HP*WP)       // 6272, channel stride in out
#define SPLANE (HH*WW)          // 3136 spatial points per (n,t)

// Scratch: exp map, [N, T, H, W]
__device__ float g_emap[NB * TT * HH * WW];

__device__ __forceinline__ unsigned long long fma2(unsigned long long a,
                                                   unsigned long long b,
                                                   unsigned long long c) {
    unsigned long long d;
    asm("fma.rn.f32x2 %0, %1, %2, %3;" : "=l"(d) : "l"(a), "l"(b), "l"(c));
    return d;
}

__device__ __forceinline__ float lo32(unsigned long long v) {
    return __uint_as_float((unsigned)v);
}
__device__ __forceinline__ float hi32(unsigned long long v) {
    return __uint_as_float((unsigned)(v >> 32));
}

// ---------------------------------------------------------------------------
// Kernel 1: emap[n,t,h,w] = exp( max_k( sum_c w[n,k,c]*vw[n,c,t,h,w] ) / 16 )
// Half-warp K-split + two spatial pairs per lane. 3 blocks/SM (97-reg cap —
// the (224,4) cap regressed). c-step 8 with two pointer streams -> 16
// outstanding LDG.64 per lane. grid (7,16,4), block (32,7).
// ---------------------------------------------------------------------------
__global__ __launch_bounds__(224, 3) void emap_kernel(const float* __restrict__ vw,
                                                      const float* __restrict__ wmat) {
    __shared__ unsigned long long wsp[CC * KK];  // [c][k], each {s,s} packed

    const int n = blockIdx.z;
    const int t = blockIdx.y;
    const int tid = threadIdx.y * 32 + threadIdx.x;

    // Load weights for this n into smem, duplicated into both f32x2 halves.
    const float* wn = wmat + (size_t)n * KK * CC;   // layout [k][c]
    for (int j = tid; j < KK * CC; j += 224) {
        int k = j >> 8;        // j = k*256 + c
        int c = j & 255;
        unsigned int si = __float_as_uint(wn[j]);
        wsp[c * KK + k] = ((unsigned long long)si << 32) | si;
    }
    __syncthreads();

    const int lane  = threadIdx.x;
    const int khalf = lane >> 4;                       // 0 or 1
    const int li    = lane & 15;
    const int wg    = blockIdx.x * 7 + threadIdx.y;    // 0..48
    const int pairA = wg * 32 + li;                    // pairs 0..15 of strip

    size_t baseA = ((size_t)n * CC * TT + t) * SPLANE + 2 * pairA;
    const unsigned long long* srcA = (const unsigned long long*)(vw + baseA);
    const unsigned long long* srcB = srcA + 16;   // +16 pairs = +32 floats

    unsigned long long accA[8], accB[8];
#pragma unroll
    for (int k = 0; k < 8; k++) { accA[k] = 0ull; accB[k] = 0ull; }

    const ulonglong2* wv = (const ulonglong2*)wsp;

    for (int c0 = 0; c0 < CC; c0 += 8) {
        unsigned long long xA[8], xB[8];
#pragma unroll
        for (int u = 0; u < 8; u++) {
            xA[u] = __ldg(srcA + (size_t)u * (PLANE / 2));
            xB[u] = __ldg(srcB + (size_t)u * (PLANE / 2));
        }
        srcA += 8 * (size_t)(PLANE / 2);
        srcB += 8 * (size_t)(PLANE / 2);
#pragma unroll
        for (int u = 0; u < 8; u++) {
            ulonglong2 wp0 = wv[(c0 + u) * (KK / 2) + khalf * 4 + 0];
            ulonglong2 wp1 = wv[(c0 + u) * (KK / 2) + khalf * 4 + 1];
            accA[0] = fma2(wp0.x, xA[u], accA[0]);
            accA[1] = fma2(wp0.y, xA[u], accA[1]);
            accB[0] = fma2(wp0.x, xB[u], accB[0]);
            accB[1] = fma2(wp0.y, xB[u], accB[1]);
            accA[2] = fma2(wp1.x, xA[u], accA[2]);
            accA[3] = fma2(wp1.y, xA[u], accA[3]);
            accB[2] = fma2(wp1.x, xB[u], accB[2]);
            accB[3] = fma2(wp1.y, xB[u], accB[3]);
            ulonglong2 wp2 = wv[(c0 + u) * (KK / 2) + khalf * 4 + 2];
            ulonglong2 wp3 = wv[(c0 + u) * (KK / 2) + khalf * 4 + 3];
            accA[4] = fma2(wp2.x, xA[u], accA[4]);
            accA[5] = fma2(wp2.y, xA[u], accA[5]);
            accB[4] = fma2(wp2.x, xB[u], accB[4]);
            accB[5] = fma2(wp2.y, xB[u], accB[5]);
            accA[6] = fma2(wp3.x, xA[u], accA[6]);
            accA[7] = fma2(wp3.y, xA[u], accA[7]);
            accB[6] = fma2(wp3.x, xB[u], accB[6]);
            accB[7] = fma2(wp3.y, xB[u], accB[7]);
        }
    }

    float mA0 = -3.4e38f, mA1 = -3.4e38f, mB0 = -3.4e38f, mB1 = -3.4e38f;
#pragma unroll
    for (int k = 0; k < 8; k++) {
        mA0 = fmaxf(mA0, lo32(accA[k]));
        mA1 = fmaxf(mA1, hi32(accA[k]));
        mB0 = fmaxf(mB0, lo32(accB[k]));
        mB1 = fmaxf(mB1, hi32(accB[k]));
    }
    mA0 = fmaxf(mA0, __shfl_xor_sync(0xffffffffu, mA0, 16));
    mA1 = fmaxf(mA1, __shfl_xor_sync(0xffffffffu, mA1, 16));
    mB0 = fmaxf(mB0, __shfl_xor_sync(0xffffffffu, mB0, 16));
    mB1 = fmaxf(mB1, __shfl_xor_sync(0xffffffffu, mB1, 16));

    if (khalf == 0) {
        size_t eidx = ((size_t)n * TT + t) * SPLANE + 2 * pairA;
        *(float2*)(g_emap + eidx) =
            make_float2(expf(mA0 * 0.0625f), expf(mA1 * 0.0625f));
        *(float2*)(g_emap + eidx + 32) =
            make_float2(expf(mB0 * 0.0625f), expf(mB1 * 0.0625f));
    }
}

// ---------------------------------------------------------------------------
// Kernel 2: out = box(vw*emap) / box(emap), stride 2, win 3, pad 1.
// Lane owns output pair (2w2, 2w2+1); per row ONE LDG.128 per channel —
// the w-1 corner term for output 2w2 is the hi-word product of lane w2-1,
// accumulated there (sp) and delivered by one shfl_up per channel AFTER
// the r-loop. L1 wavefronts per byte nearly halved vs R7.
// grid (HP, TP, NB*2), block (32,8); lane halves carry different channels,
// 2 channels per lane-iteration.
// ---------------------------------------------------------------------------
__global__ __launch_bounds__(256, 4) void pool_kernel(const float* __restrict__ vw,
                                                      float* __restrict__ out) {
    const int n     = blockIdx.z >> 1;
    const int chalf = blockIdx.z & 1;
    const int tp = blockIdx.y;
    const int hp = blockIdx.x;
    const int tid = threadIdx.y * 32 + threadIdx.x;

    __shared__ float4 wpk[9 * 14];   // {e[4w2], e[4w2+1], e[4w2+2], e[4w2+3]} per (r,w2)
    __shared__ float  wem[9 * 14];   // e[4w2-1]  (denominator only)
    __shared__ float  wrd[14 * 2];   // 1/denominator for outputs (2w2, 2w2+1)

    // Fill window-weight tables (126 items).
    if (tid < 126) {
        const int r  = tid / 14;
        const int w2 = tid - r * 14;
        const int dt = r / 3, dh = r - dt * 3;
        const int t = 2 * tp - 1 + dt;
        const int h = 2 * hp - 1 + dh;
        const bool rv = (t >= 0) && (h >= 0);
        const int tc = t > 0 ? t : 0;
        const int hc = h > 0 ? h : 0;
        const float* ep = g_emap + ((size_t)n * TT + tc) * SPLANE + (size_t)hc * WW;
        const int wb = 4 * w2;
        float em1 = (rv && wb > 0) ? ep[wb - 1] : 0.f;
        float e0 = rv ? ep[wb + 0] : 0.f;
        float e1 = rv ? ep[wb + 1] : 0.f;
        float e2 = rv ? ep[wb + 2] : 0.f;
        float e3 = rv ? ep[wb + 3] : 0.f;
        wpk[tid] = make_float4(e0, e1, e2, e3);
        wem[tid] = em1;
    }
    __syncthreads();
    if (tid < 28) {
        const int w2i = tid % 14;
        const int sel = tid / 14;
        float s = 0.f;
#pragma unroll
        for (int r = 0; r < 9; r++) {
            float4 f = wpk[r * 14 + w2i];
            s += sel ? (f.y + f.z + f.w) : (wem[r * 14 + w2i] + f.x + f.y);
        }
        wrd[w2i * 2 + sel] = 1.0f / s;
    }
    __syncthreads();

    const int lane = threadIdx.x;
    const int w2   = (lane & 15) < 14 ? (lane & 15) : 13;  // clamp
    const int csel = lane >> 4;                            // channel select 0/1
    const bool act = (lane & 15) < 14;

    const float rden0 = wrd[w2 * 2 + 0];
    const float rden1 = wrd[w2 * 2 + 1];

    int rowoff[9];
#pragma unroll
    for (int r = 0; r < 9; r++) {
        const int dt = r / 3, dh = r - dt * 3;
        const int t = 2 * tp - 1 + dt;
        const int h = 2 * hp - 1 + dh;
        const int tc = t > 0 ? t : 0;
        const int hc = h > 0 ? h : 0;
        rowoff[r] = (tc * HH + hc) * WW;
    }

    const float* basep = vw + (size_t)n * CC * PLANE + 4 * w2;
    float* outbase = out + (((size_t)n * CC * TP + tp) * HP + hp) * WP + 2 * w2;

    const int cbeg = chalf * (CC / 2);
    const ulonglong2* wpk2 = (const ulonglong2*)wpk;

    // 4 channels per warp-iteration: this lane handles cA=c0+2*csel, cB=cA+1.
    for (int c0 = cbeg + threadIdx.y * 4; c0 < cbeg + CC / 2; c0 += 32) {
        const int cA = c0 + 2 * csel;
        const float* pA = basep + (size_t)cA * PLANE;
        const float* pB = pA + PLANE;
        unsigned long long a0A = 0ull, a1A = 0ull, a0B = 0ull, a1B = 0ull;
        float sxA = 0.f, spA = 0.f, sxB = 0.f, spB = 0.f;
#pragma unroll
        for (int r = 0; r < 9; r++) {
            ulonglong2 xA = __ldg((const ulonglong2*)(pA + rowoff[r]));
            ulonglong2 xB = __ldg((const ulonglong2*)(pB + rowoff[r]));
            ulonglong2 wpr = wpk2[r * 14 + w2];   // .x = (e0,e1), .y = (e2,e3)
            a0A = fma2(wpr.x, xA.x, a0A);
            a1A = fma2(wpr.y, xA.y, a1A);
            a0B = fma2(wpr.x, xB.x, a0B);
            a1B = fma2(wpr.y, xB.y, a1B);
            sxA = fmaf(hi32(wpr.x), hi32(xA.x), sxA);   // e1*v1 -> own out1
            spA = fmaf(hi32(wpr.y), hi32(xA.y), spA);   // e3*v3 -> right nbr out0
            sxB = fmaf(hi32(wpr.x), hi32(xB.x), sxB);
            spB = fmaf(hi32(wpr.y), hi32(xB.y), spB);
        }
        float spAm = __shfl_up_sync(0xffffffffu, spA, 1);
        float spBm = __shfl_up_sync(0xffffffffu, spB, 1);
        if ((lane & 15) == 0) { spAm = 0.f; spBm = 0.f; }
        if (act) {
            float2 oA = make_float2((lo32(a0A) + hi32(a0A) + spAm) * rden0,
                                    (lo32(a1A) + hi32(a1A) + sxA) * rden1);
            float2 oB = make_float2((lo32(a0B) + hi32(a0B) + spBm) * rden0,
                                    (lo32(a1B) + hi32(a1B) + sxB) * rden1);
            *(float2*)(outbase + (size_t)cA * OPLANE) = oA;
            *(float2*)(outbase + (size_t)(cA + 1) * OPLANE) = oB;
        }
    }
}

extern "C" void kernel_launch(void* const* d_in, const int* in_sizes, int n_in,
                              void* d_out, int out_size) {
    const float* a0 = (const float*)d_in[0];
    const float* a1 = (const float*)d_in[1];
    // vw is the big tensor (51,380,224 elems); w is 16,384 elems.
    const float* vw   = (in_sizes[0] > in_sizes[1]) ? a0 : a1;
    const float* wmat = (in_sizes[0] > in_sizes[1]) ? a1 : a0;
    float* out = (float*)d_out;

    emap_kernel<<<dim3(7, TT, NB), dim3(32, 7)>>>(vw, wmat);
    pool_kernel<<<dim3(HP, TP, NB * 2), dim3(32, 8)>>>(vw, out);
}